// round 11
// baseline (speedup 1.0000x reference)
#include <cuda_runtime.h>

// ---------------------------------------------------------------------------
// MyRNN: 2-layer tanh RNN, B=4096, T=512, H=32, input dim 1, + Linear(32->1).
//
// Round-8 design (k-split, 2 warps/CTA, 2048 warps single-wave):
//   - 1024 CTAs x 64 threads. CTA owns NB=4 batches. Warp w owns the k-half
//     k in [16w, 16w+16) of every matvec -> per-lane weights 24 u64 = 48 regs
//     -> ~110 regs/thread -> 7 CTAs/SM, 13.8 warps/SM, 3.46 warps/SMSP.
//   - lane j = output hidden unit. Each warp computes k-half partial sums for
//     all 12 accumulators (3 matrices x 4 batches); partials exchanged via
//     smem; warp w finishes batches {2w, 2w+1} (tanh + state store).
//   - layer1 skewed one step behind layer0 (reads only old state).
//   - 2x bar.sync per step (7-cyc floor for 2-warp CTA).
// ---------------------------------------------------------------------------

typedef unsigned long long u64;

#define B_TOT   4096
#define T_TOT   512
#define H_DIM   32
#define NB      4
#define NCTAS   (B_TOT / NB)   // 1024

__device__ __forceinline__ u64 pk2(float x, float y) {
    u64 r; asm("mov.b64 %0, {%1,%2};" : "=l"(r) : "f"(x), "f"(y)); return r;
}
__device__ __forceinline__ void upk2(u64 v, float& x, float& y) {
    asm("mov.b64 {%0,%1}, %2;" : "=f"(x), "=f"(y) : "l"(v));
}
__device__ __forceinline__ u64 ffma2(u64 a, u64 b, u64 c) {
    u64 d; asm("fma.rn.f32x2 %0, %1, %2, %3;" : "=l"(d) : "l"(a), "l"(b), "l"(c));
    return d;
}
__device__ __forceinline__ float hsum2(u64 v) {
    float x, y; upk2(v, x, y); return x + y;
}
__device__ __forceinline__ float tanh_fast(float x) {
    x = fminf(fmaxf(x, -15.0f), 15.0f);
    float e = __expf(2.0f * x);
    return __fdividef(e - 1.0f, e + 1.0f);
}

__global__ void __launch_bounds__(64, 7)
rnn_kernel(const float* __restrict__ x,
           const float* __restrict__ hstate,
           const float* __restrict__ Wih0, const float* __restrict__ Whh0,
           const float* __restrict__ bih0, const float* __restrict__ bhh0,
           const float* __restrict__ Wih1, const float* __restrict__ Whh1,
           const float* __restrict__ bih1, const float* __restrict__ bhh1,
           const float* __restrict__ Wfc,  const float* __restrict__ bfc,
           float* __restrict__ out)
{
    // ping-pong state (CTA-shared): G0[buf][bb][j] = h0, G1 = h1
    __shared__ __align__(16) float G0[2][NB][H_DIM];
    __shared__ __align__(16) float G1[2][NB][H_DIM];
    // partial sums: P[writerWarp][t][mat][j], t indexes the 2 bbs the OTHER warp finishes
    __shared__ __align__(16) u64 P[2][2][3][H_DIM];

    const int j     = threadIdx.x & 31;     // output hidden unit
    const int w     = threadIdx.x >> 5;     // k-half owner (0 or 1)
    const int ow    = w ^ 1;
    const int kbase = 16 * w;
    const int b0    = blockIdx.x * NB;

    // ---- weights: k-half rows, k-packed u64 (8 u64 per matrix = 48 regs) ----
    u64 w0[8], wA[8], wB[8];
    {
        const u64* q0 = reinterpret_cast<const u64*>(Whh0 + j * H_DIM + kbase);
        const u64* qA = reinterpret_cast<const u64*>(Wih1 + j * H_DIM + kbase);
        const u64* qB = reinterpret_cast<const u64*>(Whh1 + j * H_DIM + kbase);
#pragma unroll
        for (int q = 0; q < 8; q++) { w0[q] = q0[q]; wA[q] = qA[q]; wB[q] = qB[q]; }
    }
    const float wi0 = Wih0[j];
    const float bb0 = bih0[j] + bhh0[j];
    const float bb1 = bih1[j] + bhh1[j];

    // ---- initial state: h0 -> buffer 0, h1 -> buffer 1 (first read at i=1) ----
    // 64 threads cover 4 bb x 32 j in 2 passes
#pragma unroll
    for (int t = 0; t < 2; t++) {
        int bb = 2 * w + t;
        G0[0][bb][j] = hstate[(b0 + bb) * H_DIM + j];
        G1[1][bb][j] = hstate[B_TOT * H_DIM + (b0 + bb) * H_DIM + j];
    }
    __syncthreads();

    // =================== i = 0 : layer0 only ===================
    {
        u64 a0[NB];
#pragma unroll
        for (int bb = 0; bb < NB; bb++) a0[bb] = 0ull;
#pragma unroll
        for (int q = 0; q < 4; q++) {
#pragma unroll
            for (int bb = 0; bb < NB; bb++) {
                ulonglong2 g = *reinterpret_cast<const ulonglong2*>(&G0[0][bb][kbase + 4 * q]);
                a0[bb] = ffma2(w0[2 * q],     g.x, a0[bb]);
                a0[bb] = ffma2(w0[2 * q + 1], g.y, a0[bb]);
            }
        }
#pragma unroll
        for (int t = 0; t < 2; t++) P[w][t][0][j] = a0[2 * ow + t];
        __syncthreads();
#pragma unroll
        for (int t = 0; t < 2; t++) {
            int bb = 2 * w + t;
            float xi = __ldg(&x[(b0 + bb) * T_TOT]);
            float s  = hsum2(a0[bb]) + hsum2(P[ow][t][0][j]) + wi0 * xi + bb0;
            G0[1][bb][j] = tanh_fast(s);
        }
        __syncthreads();
    }

    // =================== main loop i = 1 .. T-1 ===================
#pragma unroll 1
    for (int i = 1; i < T_TOT; i++) {
        const int rp = i & 1, wp = rp ^ 1;

        u64 a0[NB], aA[NB], aB[NB];
#pragma unroll
        for (int bb = 0; bb < NB; bb++) { a0[bb] = 0ull; aA[bb] = 0ull; aB[bb] = 0ull; }

#pragma unroll
        for (int q = 0; q < 4; q++) {
#pragma unroll
            for (int bb = 0; bb < NB; bb++) {
                ulonglong2 g = *reinterpret_cast<const ulonglong2*>(&G0[rp][bb][kbase + 4 * q]);
                a0[bb] = ffma2(w0[2 * q],     g.x, a0[bb]);
                a0[bb] = ffma2(w0[2 * q + 1], g.y, a0[bb]);
                aA[bb] = ffma2(wA[2 * q],     g.x, aA[bb]);
                aA[bb] = ffma2(wA[2 * q + 1], g.y, aA[bb]);
                ulonglong2 h = *reinterpret_cast<const ulonglong2*>(&G1[rp][bb][kbase + 4 * q]);
                aB[bb] = ffma2(wB[2 * q],     h.x, aB[bb]);
                aB[bb] = ffma2(wB[2 * q + 1], h.y, aB[bb]);
            }
        }

        // publish partials for the bbs the other warp finishes
#pragma unroll
        for (int t = 0; t < 2; t++) {
            int bb = 2 * ow + t;
            P[w][t][0][j] = a0[bb];
            P[w][t][1][j] = aA[bb];
            P[w][t][2][j] = aB[bb];
        }
        __syncthreads();

        // finish own bbs {2w, 2w+1}
#pragma unroll
        for (int t = 0; t < 2; t++) {
            int bb = 2 * w + t;
            float xi = __ldg(&x[(b0 + bb) * T_TOT + i]);
            float s0 = hsum2(a0[bb]) + hsum2(P[ow][t][0][j]) + wi0 * xi + bb0;
            float s1 = hsum2(aA[bb]) + hsum2(P[ow][t][1][j])
                     + hsum2(aB[bb]) + hsum2(P[ow][t][2][j]) + bb1;
            G0[wp][bb][j] = tanh_fast(s0);
            G1[wp][bb][j] = tanh_fast(s1);
        }
        __syncthreads();
    }

    // =================== i = T : layer1 only ===================
    // T even -> final states in buffer 0: G0[0]=h0(T-1), G1[0]=h1(T-2)
    float h1last[2];
    {
        u64 aA[NB], aB[NB];
#pragma unroll
        for (int bb = 0; bb < NB; bb++) { aA[bb] = 0ull; aB[bb] = 0ull; }
#pragma unroll
        for (int q = 0; q < 4; q++) {
#pragma unroll
            for (int bb = 0; bb < NB; bb++) {
                ulonglong2 g = *reinterpret_cast<const ulonglong2*>(&G0[0][bb][kbase + 4 * q]);
                aA[bb] = ffma2(wA[2 * q],     g.x, aA[bb]);
                aA[bb] = ffma2(wA[2 * q + 1], g.y, aA[bb]);
                ulonglong2 h = *reinterpret_cast<const ulonglong2*>(&G1[0][bb][kbase + 4 * q]);
                aB[bb] = ffma2(wB[2 * q],     h.x, aB[bb]);
                aB[bb] = ffma2(wB[2 * q + 1], h.y, aB[bb]);
            }
        }
#pragma unroll
        for (int t = 0; t < 2; t++) {
            int bb = 2 * ow + t;
            P[w][t][1][j] = aA[bb];
            P[w][t][2][j] = aB[bb];
        }
        __syncthreads();
#pragma unroll
        for (int t = 0; t < 2; t++) {
            int bb = 2 * w + t;
            float s1 = hsum2(aA[bb]) + hsum2(P[ow][t][1][j])
                     + hsum2(aB[bb]) + hsum2(P[ow][t][2][j]) + bb1;
            h1last[t] = tanh_fast(s1);
        }
    }

    // =================== outputs ===================
    const float wfcj = Wfc[j];
    const float bf   = bfc[0];
    float* h0out = out + B_TOT;
    float* h1out = out + B_TOT + B_TOT * H_DIM;

#pragma unroll
    for (int t = 0; t < 2; t++) {
        int bb = 2 * w + t;
        int b  = b0 + bb;
        h0out[b * H_DIM + j] = G0[0][bb][j];
        h1out[b * H_DIM + j] = h1last[t];

        float p = h1last[t] * wfcj;
#pragma unroll
        for (int m = 16; m > 0; m >>= 1)
            p += __shfl_xor_sync(0xffffffffu, p, m);
        if (j == 0) out[b] = p + bf;
    }
}

// ---------------------------------------------------------------------------
extern "C" void kernel_launch(void* const* d_in, const int* in_sizes, int n_in,
                              void* d_out, int out_size)
{
    const float* x      = (const float*)d_in[0];
    const float* hstate = (const float*)d_in[1];
    const float* Wih0   = (const float*)d_in[2];
    const float* Whh0   = (const float*)d_in[3];
    const float* bih0   = (const float*)d_in[4];
    const float* bhh0   = (const float*)d_in[5];
    const float* Wih1   = (const float*)d_in[6];
    const float* Whh1   = (const float*)d_in[7];
    const float* bih1   = (const float*)d_in[8];
    const float* bhh1   = (const float*)d_in[9];
    const float* Wfc    = (const float*)d_in[10];
    const float* bfc    = (const float*)d_in[11];
    float* out          = (float*)d_out;

    rnn_kernel<<<NCTAS, 64>>>(x, hstate, Wih0, Whh0, bih0, bhh0,
                              Wih1, Whh1, bih1, bhh1, Wfc, bfc, out);
}

// round 14
// speedup vs baseline: 1.6621x; 1.6621x over previous
#include <cuda_runtime.h>

// ---------------------------------------------------------------------------
// MyRNN: 2-layer tanh RNN, B=4096, T=512, H=32, input dim 1, + Linear(32->1).
//
// Round-12: R2 structure (NB=2, 2048 independent single-warp CTAs, skewed
// layer1, ONE __syncwarp per step, zero cross-warp coupling) register-dieted
// to <=146 regs via __launch_bounds__(32, 14) so all 2048 warps run in a
// SINGLE wave at 14 CTAs/SM (3.46 warps/SMSP). R2's only failure mode was
// 166 regs -> 12 CTAs/SM -> 2 waves.
//   - K-packed f32x2 weights in registers: 48 u64 = 96 regs.
//   - tanh via __expf identity, clamp dropped (|preact| << overflow range).
// ---------------------------------------------------------------------------

typedef unsigned long long u64;

#define B_TOT   4096
#define T_TOT   512
#define H_DIM   32
#define NB      2
#define NCTAS   (B_TOT / NB)   // 2048

__device__ __forceinline__ void upk2(u64 v, float& x, float& y) {
    asm("mov.b64 {%0,%1}, %2;" : "=f"(x), "=f"(y) : "l"(v));
}
__device__ __forceinline__ u64 ffma2(u64 a, u64 b, u64 c) {
    u64 d; asm("fma.rn.f32x2 %0, %1, %2, %3;" : "=l"(d) : "l"(a), "l"(b), "l"(c));
    return d;
}
__device__ __forceinline__ float tanh_fast(float x) {
    // |x| stays well below overflow range; no clamp needed.
    float e = __expf(2.0f * x);
    return __fdividef(e - 1.0f, e + 1.0f);
}

__global__ void __launch_bounds__(32, 14)
rnn_kernel(const float* __restrict__ x,
           const float* __restrict__ hstate,
           const float* __restrict__ Wih0, const float* __restrict__ Whh0,
           const float* __restrict__ bih0, const float* __restrict__ bhh0,
           const float* __restrict__ Wih1, const float* __restrict__ Whh1,
           const float* __restrict__ bih1, const float* __restrict__ bhh1,
           const float* __restrict__ Wfc,  const float* __restrict__ bfc,
           float* __restrict__ out)
{
    // ping-pong state: G0[buf][batch][j] = h0, G1 = h1
    __shared__ __align__(16) float G0[2][NB][H_DIM];
    __shared__ __align__(16) float G1[2][NB][H_DIM];

    const int j  = threadIdx.x;          // hidden unit
    const int b0 = blockIdx.x * NB;      // first batch element of this CTA

    // ---- weights: k-packed u64, natural memory layout (96 regs) ----
    u64 w0[H_DIM / 2], wA[H_DIM / 2], wB[H_DIM / 2];
    {
        const u64* q0 = reinterpret_cast<const u64*>(Whh0 + j * H_DIM);
        const u64* qA = reinterpret_cast<const u64*>(Wih1 + j * H_DIM);
        const u64* qB = reinterpret_cast<const u64*>(Whh1 + j * H_DIM);
#pragma unroll
        for (int q = 0; q < H_DIM / 2; q++) { w0[q] = q0[q]; wA[q] = qA[q]; wB[q] = qB[q]; }
    }
    const float wi0  = Wih0[j];
    const float bb0  = bih0[j] + bhh0[j];
    const float bb1  = bih1[j] + bhh1[j];

    // ---- initial state: h0 -> buffer 0, h1 -> buffer 1 (first read at i=1) ----
#pragma unroll
    for (int bb = 0; bb < NB; bb++) {
        G0[0][bb][j] = hstate[(b0 + bb) * H_DIM + j];
        G1[1][bb][j] = hstate[B_TOT * H_DIM + (b0 + bb) * H_DIM + j];
    }
    __syncwarp();

    // =================== i = 0 : layer0 only ===================
    {
        float xi[NB]; u64 a0[NB];
#pragma unroll
        for (int bb = 0; bb < NB; bb++) {
            xi[bb] = __ldg(&x[(b0 + bb) * T_TOT]);
            a0[bb] = 0ull;
        }
#pragma unroll
        for (int q = 0; q < 8; q++) {
#pragma unroll
            for (int bb = 0; bb < NB; bb++) {
                ulonglong2 g = *reinterpret_cast<const ulonglong2*>(&G0[0][bb][4 * q]);
                a0[bb] = ffma2(w0[2 * q],     g.x, a0[bb]);
                a0[bb] = ffma2(w0[2 * q + 1], g.y, a0[bb]);
            }
        }
#pragma unroll
        for (int bb = 0; bb < NB; bb++) {
            float lo, hi; upk2(a0[bb], lo, hi);
            G0[1][bb][j] = tanh_fast(lo + hi + wi0 * xi[bb] + bb0);
        }
        __syncwarp();
    }

    // =================== main loop i = 1 .. T-1 ===================
#pragma unroll 1
    for (int i = 1; i < T_TOT; i++) {
        const int rp = i & 1, wp = rp ^ 1;

        float xi[NB]; u64 a0[NB], aA[NB], aB[NB];
#pragma unroll
        for (int bb = 0; bb < NB; bb++) {
            xi[bb] = __ldg(&x[(b0 + bb) * T_TOT + i]);
            a0[bb] = 0ull; aA[bb] = 0ull; aB[bb] = 0ull;
        }

#pragma unroll
        for (int q = 0; q < 8; q++) {
#pragma unroll
            for (int bb = 0; bb < NB; bb++) {
                ulonglong2 g = *reinterpret_cast<const ulonglong2*>(&G0[rp][bb][4 * q]);
                a0[bb] = ffma2(w0[2 * q],     g.x, a0[bb]);
                a0[bb] = ffma2(w0[2 * q + 1], g.y, a0[bb]);
                aA[bb] = ffma2(wA[2 * q],     g.x, aA[bb]);
                aA[bb] = ffma2(wA[2 * q + 1], g.y, aA[bb]);
                ulonglong2 h = *reinterpret_cast<const ulonglong2*>(&G1[rp][bb][4 * q]);
                aB[bb] = ffma2(wB[2 * q],     h.x, aB[bb]);
                aB[bb] = ffma2(wB[2 * q + 1], h.y, aB[bb]);
            }
        }

#pragma unroll
        for (int bb = 0; bb < NB; bb++) {
            float l0, h0s; upk2(a0[bb], l0, h0s);
            float lA, hA;  upk2(aA[bb], lA, hA);
            float lB, hB;  upk2(aB[bb], lB, hB);
            G0[wp][bb][j] = tanh_fast(l0 + h0s + wi0 * xi[bb] + bb0);
            G1[wp][bb][j] = tanh_fast((lA + hA) + (lB + hB) + bb1);
        }
        __syncwarp();
    }

    // =================== i = T : layer1 only ===================
    // T even -> final states in buffer 0: G0[0]=h0(T-1), G1[0]=h1(T-2)
    float h0last[NB], h1last[NB];
    {
        u64 aA[NB], aB[NB];
#pragma unroll
        for (int bb = 0; bb < NB; bb++) { aA[bb] = 0ull; aB[bb] = 0ull; }
#pragma unroll
        for (int q = 0; q < 8; q++) {
#pragma unroll
            for (int bb = 0; bb < NB; bb++) {
                ulonglong2 g = *reinterpret_cast<const ulonglong2*>(&G0[0][bb][4 * q]);
                aA[bb] = ffma2(wA[2 * q],     g.x, aA[bb]);
                aA[bb] = ffma2(wA[2 * q + 1], g.y, aA[bb]);
                ulonglong2 h = *reinterpret_cast<const ulonglong2*>(&G1[0][bb][4 * q]);
                aB[bb] = ffma2(wB[2 * q],     h.x, aB[bb]);
                aB[bb] = ffma2(wB[2 * q + 1], h.y, aB[bb]);
            }
        }
#pragma unroll
        for (int bb = 0; bb < NB; bb++) {
            float lA, hA; upk2(aA[bb], lA, hA);
            float lB, hB; upk2(aB[bb], lB, hB);
            h1last[bb] = tanh_fast((lA + hA) + (lB + hB) + bb1);
            h0last[bb] = G0[0][bb][j];
        }
    }

    // =================== outputs ===================
    const float wfcj = Wfc[j];
    const float bf   = bfc[0];
    float* h0out = out + B_TOT;
    float* h1out = out + B_TOT + B_TOT * H_DIM;

#pragma unroll
    for (int bb = 0; bb < NB; bb++) {
        const int b = b0 + bb;
        h0out[b * H_DIM + j] = h0last[bb];
        h1out[b * H_DIM + j] = h1last[bb];

        float p = h1last[bb] * wfcj;
#pragma unroll
        for (int m = 16; m > 0; m >>= 1)
            p += __shfl_xor_sync(0xffffffffu, p, m);
        if (j == 0) out[b] = p + bf;
    }
}

// ---------------------------------------------------------------------------
extern "C" void kernel_launch(void* const* d_in, const int* in_sizes, int n_in,
                              void* d_out, int out_size)
{
    const float* x      = (const float*)d_in[0];
    const float* hstate = (const float*)d_in[1];
    const float* Wih0   = (const float*)d_in[2];
    const float* Whh0   = (const float*)d_in[3];
    const float* bih0   = (const float*)d_in[4];
    const float* bhh0   = (const float*)d_in[5];
    const float* Wih1   = (const float*)d_in[6];
    const float* Whh1   = (const float*)d_in[7];
    const float* bih1   = (const float*)d_in[8];
    const float* bhh1   = (const float*)d_in[9];
    const float* Wfc    = (const float*)d_in[10];
    const float* bfc    = (const float*)d_in[11];
    float* out          = (float*)d_out;

    rnn_kernel<<<NCTAS, 32>>>(x, hstate, Wih0, Whh0, bih0, bhh0,
                              Wih1, Whh1, bih1, bhh1, Wfc, bfc, out);
}

// round 15
// speedup vs baseline: 3.6030x; 2.1678x over previous
#include <cuda_runtime.h>

// ---------------------------------------------------------------------------
// MyRNN: 2-layer tanh RNN, B=4096, T=512, H=32, input dim 1, + Linear(32->1).
//
// Round-15: tensor-core engine. The fp32 f32x2 path is walled at ~400us
// (FFMA2 rt=4 => no gain over scalar). Replace all matvecs with
// mma.sync.m16n8k16 bf16 using hi/lo split precision:
//     W*h ~= Whi*hhi + Whi*hlo + Wlo*hhi   (fp32 accumulate, err ~1e-5)
// One warp owns 8 batches. Per step: 36 HMMA + 16 tanh.
//   - Weights as persistent A-fragments (hi+lo) in registers.
//   - h state redistributed D-layout -> B-layout via warp-private smem
//     ([batch][k] fp32, row stride 36 => conflict-free stores, <=2-way loads).
//   - layer1 skewed one step behind layer0; double-buffered state;
//     ONE __syncwarp per step; no CTA barriers.
//   - 128 CTAs x 128 threads (512 warps) -> 1 CTA/SM, single wave.
// ---------------------------------------------------------------------------

typedef unsigned int u32;

#define B_TOT 4096
#define T_TOT 512
#define H     32
#define WPC   4                 // warps per CTA
#define NCTAS (B_TOT / (8 * WPC))   // 128
#define SROW  36                // padded row stride (floats) for h smem [b][k]

// pack two f32 -> bf16x2 ; first arg -> LOW half, second -> HIGH half
__device__ __forceinline__ u32 bf16pair(float flo, float fhi) {
    u32 d;
    asm("cvt.rn.bf16x2.f32 %0, %1, %2;" : "=r"(d) : "f"(fhi), "f"(flo));
    return d;
}
__device__ __forceinline__ float lo_f32(u32 p) { return __uint_as_float(p << 16); }
__device__ __forceinline__ float hi_f32(u32 p) { return __uint_as_float(p & 0xffff0000u); }

struct Frag { u32 h[4]; u32 l[4]; };   // A-fragment (16x16 bf16), hi + lo parts

__device__ __forceinline__ void mma_bf16(float* d, const u32* a, const u32* b) {
    asm("mma.sync.aligned.m16n8k16.row.col.f32.bf16.bf16.f32 "
        "{%0,%1,%2,%3}, {%4,%5,%6,%7}, {%8,%9}, {%0,%1,%2,%3};"
        : "+f"(d[0]), "+f"(d[1]), "+f"(d[2]), "+f"(d[3])
        : "r"(a[0]), "r"(a[1]), "r"(a[2]), "r"(a[3]), "r"(b[0]), "r"(b[1]));
}

__device__ __forceinline__ float tanh_fast(float x) {
    float e = __expf(2.0f * x);
    return __fdividef(e - 1.0f, e + 1.0f);
}

// Load A-fragment (hi/lo) of 32x32 row-major W, tile (mt, kt).
// A layout (m16n8k16): reg0 = (r0, c0..c0+1), reg1 = (r0+8, c0..c0+1),
//                      reg2 = (r0, c0+8..9),  reg3 = (r0+8, c0+8..9)
__device__ __forceinline__ Frag load_frag(const float* __restrict__ W,
                                          int mt, int kt, int g, int tu) {
    Frag f;
    const int r0 = 16 * mt + g, r1 = r0 + 8, c = 16 * kt + 2 * tu;
    float v[8];
    v[0] = W[r0 * H + c];     v[1] = W[r0 * H + c + 1];
    v[2] = W[r1 * H + c];     v[3] = W[r1 * H + c + 1];
    v[4] = W[r0 * H + c + 8]; v[5] = W[r0 * H + c + 9];
    v[6] = W[r1 * H + c + 8]; v[7] = W[r1 * H + c + 9];
#pragma unroll
    for (int q = 0; q < 4; q++) {
        f.h[q] = bf16pair(v[2 * q], v[2 * q + 1]);
        f.l[q] = bf16pair(v[2 * q] - lo_f32(f.h[q]), v[2 * q + 1] - hi_f32(f.h[q]));
    }
    return f;
}

// Build B-fragments (hi/lo) for h (32 k x 8 n) from smem [b][k] (stride SROW).
// B layout: per k-tile kt: reg0 = (k=16kt+2tu, +1; n=g), reg1 = (k=16kt+2tu+8, +9; n=g)
__device__ __forceinline__ void build_b(u32 bh[2][2], u32 bl[2][2],
                                        const float* __restrict__ hsm, int g, int tu) {
#pragma unroll
    for (int kt = 0; kt < 2; kt++) {
        float f0 = hsm[g * SROW + 16 * kt + 2 * tu];
        float f1 = hsm[g * SROW + 16 * kt + 2 * tu + 1];
        float f2 = hsm[g * SROW + 16 * kt + 2 * tu + 8];
        float f3 = hsm[g * SROW + 16 * kt + 2 * tu + 9];
        bh[kt][0] = bf16pair(f0, f1);
        bh[kt][1] = bf16pair(f2, f3);
        bl[kt][0] = bf16pair(f0 - lo_f32(bh[kt][0]), f1 - hi_f32(bh[kt][0]));
        bl[kt][1] = bf16pair(f2 - lo_f32(bh[kt][1]), f3 - hi_f32(bh[kt][1]));
    }
}

// One split matvec: d += W * h  (3 mma terms per (mt, kt))
__device__ __forceinline__ void mv(float d[2][4], const Frag W[2][2],
                                   const u32 bh[2][2], const u32 bl[2][2]) {
#pragma unroll
    for (int mt = 0; mt < 2; mt++)
#pragma unroll
        for (int kt = 0; kt < 2; kt++) {
            mma_bf16(d[mt], W[mt][kt].h, bh[kt]);
            mma_bf16(d[mt], W[mt][kt].h, bl[kt]);
            mma_bf16(d[mt], W[mt][kt].l, bh[kt]);
        }
}

// Store tanh'd D values (2 tiles x 4 regs) to smem [b][k].
// D layout: d0=(r0,c0) d1=(r0,c0+1) d2=(r0+8,c0) d3=(r0+8,c0+1), r0=g+16mt, c0=2tu
__device__ __forceinline__ void store_h(float* __restrict__ hsm, int g, int tu,
                                        const float v[2][4]) {
#pragma unroll
    for (int mt = 0; mt < 2; mt++) {
        hsm[(2 * tu + 0) * SROW + g + 16 * mt]     = v[mt][0];
        hsm[(2 * tu + 1) * SROW + g + 16 * mt]     = v[mt][1];
        hsm[(2 * tu + 0) * SROW + g + 8 + 16 * mt] = v[mt][2];
        hsm[(2 * tu + 1) * SROW + g + 8 + 16 * mt] = v[mt][3];
    }
}

__global__ void __launch_bounds__(128, 1)
rnn_kernel(const float* __restrict__ x,
           const float* __restrict__ hstate,
           const float* __restrict__ Wih0, const float* __restrict__ Whh0,
           const float* __restrict__ bih0, const float* __restrict__ bhh0,
           const float* __restrict__ Wih1, const float* __restrict__ Whh1,
           const float* __restrict__ bih1, const float* __restrict__ bhh1,
           const float* __restrict__ Wfc,  const float* __restrict__ bfc,
           float* __restrict__ out)
{
    // [warp][buffer][layer][8 batches x SROW]
    __shared__ float HSm[WPC][2][2][8 * SROW];

    const int lane = threadIdx.x & 31;
    const int wid  = threadIdx.x >> 5;
    const int g    = lane >> 2;     // 0..7
    const int tu   = lane & 3;      // 0..3
    const int b0   = (blockIdx.x * WPC + wid) * 8;

    // ---- persistent weight fragments (hi+lo): 96 regs ----
    Frag w0[2][2], wa[2][2], wb[2][2];
#pragma unroll
    for (int mt = 0; mt < 2; mt++)
#pragma unroll
        for (int kt = 0; kt < 2; kt++) {
            w0[mt][kt] = load_frag(Whh0, mt, kt, g, tu);
            wa[mt][kt] = load_frag(Wih1, mt, kt, g, tu);
            wb[mt][kt] = load_frag(Whh1, mt, kt, g, tu);
        }

    // per-thread biases / input weights at rows r0 = g+16mt, r1 = r0+8
    float bia0[2][2], bia1[2][2], wx[2][2];
#pragma unroll
    for (int mt = 0; mt < 2; mt++) {
        int r0 = g + 16 * mt, r1 = r0 + 8;
        bia0[mt][0] = bih0[r0] + bhh0[r0];
        bia0[mt][1] = bih0[r1] + bhh0[r1];
        bia1[mt][0] = bih1[r0] + bhh1[r0];
        bia1[mt][1] = bih1[r1] + bhh1[r1];
        wx[mt][0] = Wih0[r0];
        wx[mt][1] = Wih0[r1];
    }

    // x pointers for this thread's two batch columns
    const float* px0 = x + (size_t)(b0 + 2 * tu) * T_TOT;
    const float* px1 = px0 + T_TOT;

    // ---- initial state into smem: h0init -> buf1/layer0, h1init -> buf0/layer1 ----
    // lane covers n = g, k = 8*tu .. 8*tu+7
#pragma unroll
    for (int kk = 0; kk < 8; kk++) {
        int k = 8 * tu + kk;
        HSm[wid][1][0][g * SROW + k] = hstate[(b0 + g) * H + k];
        HSm[wid][0][1][g * SROW + k] = hstate[B_TOT * H + (b0 + g) * H + k];
    }
    __syncwarp();

    float h0v[2][4], h1v[2][4];

    // =================== i = 0 : layer0 only ===================
    {
        float xa = __ldg(px0 + 0), xb = __ldg(px1 + 0);
        u32 b0h[2][2], b0l[2][2];
        build_b(b0h, b0l, &HSm[wid][1][0][0], g, tu);
        float d0[2][4];
#pragma unroll
        for (int mt = 0; mt < 2; mt++) {
            d0[mt][0] = fmaf(wx[mt][0], xa, bia0[mt][0]);
            d0[mt][1] = fmaf(wx[mt][0], xb, bia0[mt][0]);
            d0[mt][2] = fmaf(wx[mt][1], xa, bia0[mt][1]);
            d0[mt][3] = fmaf(wx[mt][1], xb, bia0[mt][1]);
        }
        mv(d0, w0, b0h, b0l);
#pragma unroll
        for (int mt = 0; mt < 2; mt++)
#pragma unroll
            for (int q = 0; q < 4; q++) h0v[mt][q] = tanh_fast(d0[mt][q]);
        store_h(&HSm[wid][0][0][0], g, tu, h0v);
        __syncwarp();
    }

    // =================== main loop i = 1 .. T-1 ===================
    // read buf (i-1)&1 : { h0(i-1), h1(i-2) } ; write buf i&1 : { h0(i), h1(i-1) }
#pragma unroll 1
    for (int i = 1; i < T_TOT; i++) {
        const int rp = (i - 1) & 1, wp = i & 1;
        float xa = __ldg(px0 + i), xb = __ldg(px1 + i);

        u32 b0h[2][2], b0l[2][2], b1h[2][2], b1l[2][2];
        build_b(b0h, b0l, &HSm[wid][rp][0][0], g, tu);
        build_b(b1h, b1l, &HSm[wid][rp][1][0], g, tu);

        float d0[2][4], d1[2][4];
#pragma unroll
        for (int mt = 0; mt < 2; mt++) {
            d0[mt][0] = fmaf(wx[mt][0], xa, bia0[mt][0]);
            d0[mt][1] = fmaf(wx[mt][0], xb, bia0[mt][0]);
            d0[mt][2] = fmaf(wx[mt][1], xa, bia0[mt][1]);
            d0[mt][3] = fmaf(wx[mt][1], xb, bia0[mt][1]);
            d1[mt][0] = bia1[mt][0];
            d1[mt][1] = bia1[mt][0];
            d1[mt][2] = bia1[mt][1];
            d1[mt][3] = bia1[mt][1];
        }

        mv(d0, w0, b0h, b0l);   // layer0: Whh0 * h0(i-1)
        mv(d1, wa, b0h, b0l);   // layer1: Wih1 * h0(i-1)
        mv(d1, wb, b1h, b1l);   // layer1: Whh1 * h1(i-2)

#pragma unroll
        for (int mt = 0; mt < 2; mt++)
#pragma unroll
            for (int q = 0; q < 4; q++) {
                h0v[mt][q] = tanh_fast(d0[mt][q]);
                h1v[mt][q] = tanh_fast(d1[mt][q]);
            }
        store_h(&HSm[wid][wp][0][0], g, tu, h0v);
        store_h(&HSm[wid][wp][1][0], g, tu, h1v);
        __syncwarp();
    }

    // =================== final : layer1 for step T-1 ===================
    // buf 1 holds { h0(T-1), h1(T-2) }  (T-1 = 511 is odd -> wp was 1)
    {
        u32 b0h[2][2], b0l[2][2], b1h[2][2], b1l[2][2];
        build_b(b0h, b0l, &HSm[wid][1][0][0], g, tu);
        build_b(b1h, b1l, &HSm[wid][1][1][0], g, tu);
        float d1[2][4];
#pragma unroll
        for (int mt = 0; mt < 2; mt++) {
            d1[mt][0] = bia1[mt][0];
            d1[mt][1] = bia1[mt][0];
            d1[mt][2] = bia1[mt][1];
            d1[mt][3] = bia1[mt][1];
        }
        mv(d1, wa, b0h, b0l);
        mv(d1, wb, b1h, b1l);
#pragma unroll
        for (int mt = 0; mt < 2; mt++)
#pragma unroll
            for (int q = 0; q < 4; q++) h1v[mt][q] = tanh_fast(d1[mt][q]);
    }

    // =================== outputs ===================
    float* h0out = out + B_TOT;
    float* h1out = out + B_TOT + B_TOT * H;
    const int c0 = b0 + 2 * tu, c1 = c0 + 1;
#pragma unroll
    for (int mt = 0; mt < 2; mt++) {
        int r0 = g + 16 * mt, r1 = r0 + 8;
        h0out[c0 * H + r0] = h0v[mt][0];
        h0out[c1 * H + r0] = h0v[mt][1];
        h0out[c0 * H + r1] = h0v[mt][2];
        h0out[c1 * H + r1] = h0v[mt][3];
        h1out[c0 * H + r0] = h1v[mt][0];
        h1out[c1 * H + r0] = h1v[mt][1];
        h1out[c0 * H + r1] = h1v[mt][2];
        h1out[c1 * H + r1] = h1v[mt][3];
    }

    // pred[b] = sum_j Wfc[j] * h1[j, b] + bfc
    float pa = 0.0f, pb = 0.0f;
#pragma unroll
    for (int mt = 0; mt < 2; mt++) {
        float wf0 = Wfc[g + 16 * mt], wf1 = Wfc[g + 8 + 16 * mt];
        pa = fmaf(wf0, h1v[mt][0], fmaf(wf1, h1v[mt][2], pa));
        pb = fmaf(wf0, h1v[mt][1], fmaf(wf1, h1v[mt][3], pb));
    }
#pragma unroll
    for (int m = 4; m <= 16; m <<= 1) {
        pa += __shfl_xor_sync(0xffffffffu, pa, m);
        pb += __shfl_xor_sync(0xffffffffu, pb, m);
    }
    if (lane < 4) {
        float bf = bfc[0];
        out[b0 + 2 * lane]     = pa + bf;
        out[b0 + 2 * lane + 1] = pb + bf;
    }
}

// ---------------------------------------------------------------------------
extern "C" void kernel_launch(void* const* d_in, const int* in_sizes, int n_in,
                              void* d_out, int out_size)
{
    const float* x      = (const float*)d_in[0];
    const float* hstate = (const float*)d_in[1];
    const float* Wih0   = (const float*)d_in[2];
    const float* Whh0   = (const float*)d_in[3];
    const float* bih0   = (const float*)d_in[4];
    const float* bhh0   = (const float*)d_in[5];
    const float* Wih1   = (const float*)d_in[6];
    const float* Whh1   = (const float*)d_in[7];
    const float* bih1   = (const float*)d_in[8];
    const float* bhh1   = (const float*)d_in[9];
    const float* Wfc    = (const float*)d_in[10];
    const float* bfc    = (const float*)d_in[11];
    float* out          = (float*)d_out;

    rnn_kernel<<<NCTAS, 128>>>(x, hstate, Wih0, Whh0, bih0, bhh0,
                               Wih1, Whh1, bih1, bhh1, Wfc, bfc, out);
}